// round 8
// baseline (speedup 1.0000x reference)
#include <cuda_runtime.h>
#include <math.h>

#define BATCH 2
#define H0 512
#define W0 512
#define HW0 (H0*W0)
#define HW1 (256*256)
#define HW2 (128*128)

typedef unsigned long long u64;

// ---------------- scratch (device globals; no allocations allowed) ----------------
// dual-image layout: [img0 batch slab][img1 batch slab]
__device__ float g_t1[2*BATCH*32*HW0];
__device__ float g_f1[2*BATCH*32*HW0];
__device__ float g_t2[2*BATCH*64*HW1];
__device__ float g_f2[2*BATCH*64*HW1];
__device__ float g_t3[2*BATCH*96*HW2];
__device__ float g_f3[2*BATCH*96*HW2];
__device__ float g_z [2*BATCH*HW0];      // z maps, both directions
__device__ float g_zr[2*BATCH*HW1];      // resized z
__device__ float g_acc[2*BATCH*3*HW0];   // splat accumulators, both directions

// ---------------- packed f32x2 helpers ----------------
__device__ __forceinline__ u64 dup2(float v) {
    u64 r; asm("mov.b64 %0, {%1, %1};" : "=l"(r) : "f"(v)); return r;
}
__device__ __forceinline__ u64 pack2(float lo, float hi) {
    u64 r; asm("mov.b64 %0, {%1, %2};" : "=l"(r) : "f"(lo), "f"(hi)); return r;
}
__device__ __forceinline__ void ffma2(u64 &acc, u64 w, u64 v) {
    asm("fma.rn.f32x2 %0, %1, %2, %0;" : "+l"(acc) : "l"(w), "l"(v));
}
__device__ __forceinline__ float2 unp2(u64 a) {
    float2 r; asm("mov.b64 {%0, %1}, %2;" : "=f"(r.x), "=f"(r.y) : "l"(a)); return r;
}

// ---------------- conv3x3 + PReLU, v3 ----------------
// 128 threads/block, 4 consecutive output pixels x 8 output channels per thread
// (channel pairs packed into f32x2 accumulators, FFMA2 path).
// Input loads: one LDG.128 per row (+1 for stride2); halo values from warp shuffles
// (warps never straddle rows: all Wout are multiples of 128). Edge lanes use
// predicated scalar loads. Both images processed in one launch (blockIdx.z).
template<int STRIDE>
__global__ void __launch_bounds__(128)
conv3x3_v3(const float* __restrict__ inA, const float* __restrict__ inB,
           const float* __restrict__ wgt, const float* __restrict__ bias,
           const float* __restrict__ prelu_a, int aidx,
           float* __restrict__ outA, float* __restrict__ outB,
           int Cin, int Cout, int Hin, int Win, int Hout, int Wout)
{
    extern __shared__ u64 w_s[];   // [Cin][9 taps][4 channel-pairs]
    const int tid = threadIdx.x;
    const int zz = blockIdx.z;                 // 0..2*BATCH-1
    const int b  = zz & (BATCH - 1);
    const float* in  = (zz < BATCH) ? inA  : inB;
    float*       out = (zz < BATCH) ? outA : outB;
    const int co_base = blockIdx.y * 8;
    const int nW = Cin * 9;

    for (int i = tid; i < Cin * 36; i += 128) {
        int q = i & 3, rest = i >> 2;
        int tap = rest % 9, ci = rest / 9;
        w_s[i] = pack2(wgt[(size_t)(co_base + 2*q    ) * nW + ci*9 + tap],
                       wgt[(size_t)(co_base + 2*q + 1) * nW + ci*9 + tap]);
    }
    __syncthreads();

    const int base = (blockIdx.x * 128 + tid) * 4;   // 4 consecutive output pixels
    const int oy = base / Wout;
    const int ox = base - oy * Wout;
    const int lane = tid & 31;
    const int bx = ox * STRIDE;                      // input x of first pixel

    u64 acc[4][4];
    #pragma unroll
    for (int p = 0; p < 4; p++)
        #pragma unroll
        for (int q = 0; q < 4; q++) acc[p][q] = 0ULL;

    const int HWin = Hin * Win;
    const float* chan = in + (size_t)b * Cin * HWin;

    for (int ci = 0; ci < Cin; ci++, chan += HWin) {
        const u64* wrow = w_s + ci * 36;
        #pragma unroll
        for (int r = 0; r < 3; r++) {
            const int iy = oy * STRIDE + r - 1;
            if ((unsigned)iy >= (unsigned)Hin) continue;   // warp-uniform
            const float* row = chan + (size_t)iy * Win;
            if (STRIDE == 1) {
                float4 Cv = __ldg((const float4*)(row + bx));
                float vm1 = __shfl_up_sync(0xffffffffu, Cv.w, 1);
                if (lane == 0) vm1 = (ox > 0) ? __ldg(row + bx - 1) : 0.f;
                float v4 = __shfl_down_sync(0xffffffffu, Cv.x, 1);
                if (lane == 31) v4 = (bx + 4 < Win) ? __ldg(row + bx + 4) : 0.f;
                u64 vd[6];
                vd[0] = dup2(vm1);  vd[1] = dup2(Cv.x); vd[2] = dup2(Cv.y);
                vd[3] = dup2(Cv.z); vd[4] = dup2(Cv.w); vd[5] = dup2(v4);
                #pragma unroll
                for (int dx = 0; dx < 3; dx++) {
                    const u64* wt = wrow + (r * 3 + dx) * 4;
                    u64 w0 = wt[0], w1 = wt[1], w2 = wt[2], w3 = wt[3];
                    #pragma unroll
                    for (int p = 0; p < 4; p++) {
                        u64 vv = vd[p + dx];
                        ffma2(acc[p][0], w0, vv); ffma2(acc[p][1], w1, vv);
                        ffma2(acc[p][2], w2, vv); ffma2(acc[p][3], w3, vv);
                    }
                }
            } else {
                float4 C0 = __ldg((const float4*)(row + bx));
                float4 C1 = __ldg((const float4*)(row + bx + 4));
                float vm1 = __shfl_up_sync(0xffffffffu, C1.w, 1);   // prev lane: x = bx-1
                if (lane == 0) vm1 = (ox > 0) ? __ldg(row + bx - 1) : 0.f;
                float v8 = __shfl_down_sync(0xffffffffu, C0.x, 1);  // next lane: x = bx+8
                if (lane == 31) v8 = (bx + 8 < Win) ? __ldg(row + bx + 8) : 0.f;
                u64 vd[10];
                vd[0] = dup2(vm1);
                vd[1] = dup2(C0.x); vd[2] = dup2(C0.y); vd[3] = dup2(C0.z); vd[4] = dup2(C0.w);
                vd[5] = dup2(C1.x); vd[6] = dup2(C1.y); vd[7] = dup2(C1.z); vd[8] = dup2(C1.w);
                vd[9] = dup2(v8);
                #pragma unroll
                for (int dx = 0; dx < 3; dx++) {
                    const u64* wt = wrow + (r * 3 + dx) * 4;
                    u64 w0 = wt[0], w1 = wt[1], w2 = wt[2], w3 = wt[3];
                    #pragma unroll
                    for (int p = 0; p < 4; p++) {
                        u64 vv = vd[2 * p + dx];
                        ffma2(acc[p][0], w0, vv); ffma2(acc[p][1], w1, vv);
                        ffma2(acc[p][2], w2, vv); ffma2(acc[p][3], w3, vv);
                    }
                }
            }
        }
    }

    const float alpha = prelu_a[aidx];
    const int HWout = Hout * Wout;
    float* ob = out + ((size_t)b * Cout + co_base) * HWout + base;
    #pragma unroll
    for (int q = 0; q < 4; q++) {
        float blo = bias[co_base + 2*q], bhi = bias[co_base + 2*q + 1];
        float4 olo, ohi;
        float* plo = &olo.x; float* phi = &ohi.x;
        #pragma unroll
        for (int p = 0; p < 4; p++) {
            float2 a = unp2(acc[p][q]);
            float rl = a.x + blo; rl = (rl >= 0.f) ? rl : alpha * rl;
            float rh = a.y + bhi; rh = (rh >= 0.f) ? rh : alpha * rh;
            plo[p] = rl; phi[p] = rh;
        }
        *(float4*)(ob + (size_t)(2*q    ) * HWout) = olo;
        *(float4*)(ob + (size_t)(2*q + 1) * HWout) = ohi;
    }
}

// ---------------- z maps, both directions in one launch ----------------
__global__ void compute_z_k(const float* __restrict__ in0,
                            const float* __restrict__ in1,
                            const float* __restrict__ flow01,
                            const float* __restrict__ flow10,
                            const float* __restrict__ pscale,
                            float* __restrict__ z, int H, int W)
{
    const int zz = blockIdx.y;              // 0..2*BATCH-1
    const int d = zz / BATCH, b = zz % BATCH;
    const int p = blockIdx.x * blockDim.x + threadIdx.x;
    const int HW = H * W;
    if (p >= HW) return;
    const int y = p / W;
    const int x = p - y * W;

    const float* i0 = d ? in1 : in0;
    const float* i1 = d ? in0 : in1;
    const float* flow = d ? flow10 : flow01;

    const float fx = flow[((size_t)b * 2 + 0) * HW + p];
    const float fy = flow[((size_t)b * 2 + 1) * HW + p];
    float px = fminf(fmaxf((float)x + fx, 0.f), (float)(W - 1));
    float py = fminf(fmaxf((float)y + fy, 0.f), (float)(H - 1));
    float x0f = floorf(px), y0f = floorf(py);
    int x0 = (int)x0f, y0 = (int)y0f;
    int x1 = min(x0 + 1, W - 1), y1 = min(y0 + 1, H - 1);
    float wx = px - x0f, wy = py - y0f;
    float w00 = (1.f - wx) * (1.f - wy);
    float w10 = wx * (1.f - wy);
    float w01 = (1.f - wx) * wy;
    float w11 = wx * wy;

    float err = 0.f;
    #pragma unroll
    for (int c = 0; c < 3; c++) {
        const float* s = i1 + ((size_t)b * 3 + c) * HW;
        float g = s[y0 * W + x0] * w00 + s[y0 * W + x1] * w10 +
                  s[y1 * W + x0] * w01 + s[y1 * W + x1] * w11;
        float a = i0[((size_t)b * 3 + c) * HW + p];
        err += fabsf((2.f * a - 1.f) - (2.f * g - 1.f));
    }
    z[(size_t)zz * HW + p] = pscale[0] * (err * (1.f / 3.f));
}

// ---------------- bilinear resize of z, all 4 (d,b) slabs ----------------
__global__ void resize1_k(const float* __restrict__ in, float* __restrict__ out,
                          int Hin, int Win, int Hout, int Wout)
{
    const int zz = blockIdx.y;
    const int p = blockIdx.x * blockDim.x + threadIdx.x;
    const int HWo = Hout * Wout;
    if (p >= HWo) return;
    const int y = p / Wout;
    const int x = p - y * Wout;

    const float ry = (float)Hin / (float)Hout;
    const float rx = (float)Win / (float)Wout;
    float py = fminf(fmaxf(((float)y + 0.5f) * ry - 0.5f, 0.f), (float)(Hin - 1));
    float px = fminf(fmaxf(((float)x + 0.5f) * rx - 0.5f, 0.f), (float)(Win - 1));
    float y0f = floorf(py), x0f = floorf(px);
    int y0 = (int)y0f, x0 = (int)x0f;
    int y1 = min(y0 + 1, Hin - 1), x1 = min(x0 + 1, Win - 1);
    float wy = py - y0f, wx = px - x0f;

    const float* s = in + (size_t)zz * Hin * Win;
    float top = s[y0 * Win + x0] * (1.f - wx) + s[y0 * Win + x1] * wx;
    float bot = s[y1 * Win + x0] * (1.f - wx) + s[y1 * Win + x1] * wx;
    out[(size_t)zz * HWo + p] = top * (1.f - wy) + bot * wy;
}

// ---------------- softsplat scatter, both directions in one launch ----------------
__global__ void splat_k(const float* __restrict__ flowA,
                        const float* __restrict__ flowB,
                        const float* __restrict__ zmap,
                        const float* __restrict__ tt,
                        float* __restrict__ acc, int H, int W)
{
    const int zz = blockIdx.y;
    const int d = zz / BATCH, b = zz % BATCH;
    const int p = blockIdx.x * blockDim.x + threadIdx.x;
    const int HW = H * W;
    if (p >= HW) return;
    const int y = p / W;
    const int x = p - y * W;

    const float* flow = d ? flowB : flowA;
    float t = tt[b];
    if (d) t = 1.f - t;
    const float fx = t * flow[((size_t)b * 2 + 0) * HW + p];
    const float fy = t * flow[((size_t)b * 2 + 1) * HW + p];
    const float ez = expf(zmap[(size_t)zz * HW + p]);
    const float v0 = -fx * ez;
    const float v1 = -fy * ez;

    const float X = (float)x + fx;
    const float Y = (float)y + fy;
    const float x0f = floorf(X), y0f = floorf(Y);
    const int x0 = (int)x0f, y0 = (int)y0f;
    const float wx1 = X - x0f, wy1 = Y - y0f;
    const float wx0 = 1.f - wx1, wy0 = 1.f - wy1;

    float* a0 = acc + ((size_t)zz * 3 + 0) * HW;
    float* a1 = acc + ((size_t)zz * 3 + 1) * HW;
    float* a2 = acc + ((size_t)zz * 3 + 2) * HW;

    int cxs[4] = {x0, x0 + 1, x0,     x0 + 1};
    int cys[4] = {y0, y0,     y0 + 1, y0 + 1};
    float cws[4] = {wx0 * wy0, wx1 * wy0, wx0 * wy1, wx1 * wy1};
    #pragma unroll
    for (int k = 0; k < 4; k++) {
        int cx = cxs[k], cy = cys[k];
        if (cx >= 0 && cx < W && cy >= 0 && cy < H) {
            int idx = cy * W + cx;
            float cw = cws[k];
            atomicAdd(a0 + idx, v0 * cw);
            atomicAdd(a1 + idx, v1 * cw);
            atomicAdd(a2 + idx, ez * cw);
        }
    }
}

// ---------------- fused normalize + backwarp (feat, and img at s=0) ----------------
__global__ void backwarp_norm_k(const float* __restrict__ acc,
                                const float* __restrict__ featA,
                                const float* __restrict__ featB,
                                const float* __restrict__ imgA,   // null if s>0
                                const float* __restrict__ imgB,
                                float* __restrict__ out,          // level base
                                int C, int H, int W, int chTot,
                                int fOffA, int fOffB, int iOffA, int iOffB)
{
    const int zz = blockIdx.y;
    const int d = zz / BATCH, b = zz % BATCH;
    const int p = blockIdx.x * blockDim.x + threadIdx.x;
    const int HW = H * W;
    if (p >= HW) return;
    const int y = p / W;
    const int x = p - y * W;

    const float* a = acc + (size_t)zz * 3 * HW;
    float inv = 1.f / (a[2 * (size_t)HW + p] + 1e-7f);
    const float fx = a[p] * inv;
    const float fy = a[(size_t)HW + p] * inv;

    float px = fminf(fmaxf((float)x + fx, 0.f), (float)(W - 1));
    float py = fminf(fmaxf((float)y + fy, 0.f), (float)(H - 1));
    float x0f = floorf(px), y0f = floorf(py);
    int x0 = (int)x0f, y0 = (int)y0f;
    int x1 = min(x0 + 1, W - 1), y1 = min(y0 + 1, H - 1);
    float wx = px - x0f, wy = py - y0f;
    float w00 = (1.f - wx) * (1.f - wy);
    float w10 = wx * (1.f - wy);
    float w01 = (1.f - wx) * wy;
    float w11 = wx * wy;
    int i00 = y0 * W + x0, i10 = y0 * W + x1;
    int i01 = y1 * W + x0, i11 = y1 * W + x1;

    const float* feat = (d ? featB : featA) + (size_t)b * C * HW;
    const int fOff = d ? fOffB : fOffA;
    for (int c = 0; c < C; c++) {
        const float* s = feat + (size_t)c * HW;
        float g = s[i00] * w00 + s[i10] * w10 + s[i01] * w01 + s[i11] * w11;
        out[((size_t)b * chTot + fOff + c) * HW + p] = g;
    }
    if (imgA) {
        const float* img = (d ? imgB : imgA) + (size_t)b * 3 * HW;
        const int iOff = d ? iOffB : iOffA;
        #pragma unroll
        for (int c = 0; c < 3; c++) {
            const float* s = img + (size_t)c * HW;
            float g = s[i00] * w00 + s[i10] * w10 + s[i01] * w01 + s[i11] * w11;
            out[((size_t)b * chTot + iOff + c) * HW + p] = g;
        }
    }
}

// ---------------- host orchestration ----------------
static void launch_conv(const float* inA, const float* inB,
                        const float* w, const float* bias,
                        const float* prelu_a, int aidx,
                        float* outA, float* outB,
                        int Cin, int Cout, int Hin, int Win, int stride)
{
    int Hout = Hin / stride, Wout = Win / stride;
    dim3 grid((Hout * Wout) / 512, Cout / 8, 2 * BATCH);
    size_t smem = (size_t)Cin * 36 * sizeof(u64);
    if (stride == 1)
        conv3x3_v3<1><<<grid, 128, smem>>>(inA, inB, w, bias, prelu_a, aidx,
                                           outA, outB, Cin, Cout, Hin, Win, Hout, Wout);
    else
        conv3x3_v3<2><<<grid, 128, smem>>>(inA, inB, w, bias, prelu_a, aidx,
                                           outA, outB, Cin, Cout, Hin, Win, Hout, Wout);
}

extern "C" void kernel_launch(void* const* d_in, const int* in_sizes, int n_in,
                              void* d_out, int out_size)
{
    const float* in0   = (const float*)d_in[0];
    const float* in1   = (const float*)d_in[1];
    const float* tt    = (const float*)d_in[2];
    const float* flow01[3] = {(const float*)d_in[3], (const float*)d_in[4], (const float*)d_in[5]};
    const float* flow10[3] = {(const float*)d_in[6], (const float*)d_in[7], (const float*)d_in[8]};
    const float* W_[6]  = {(const float*)d_in[9],  (const float*)d_in[11], (const float*)d_in[13],
                           (const float*)d_in[15], (const float*)d_in[17], (const float*)d_in[19]};
    const float* Bi[6]  = {(const float*)d_in[10], (const float*)d_in[12], (const float*)d_in[14],
                           (const float*)d_in[16], (const float*)d_in[18], (const float*)d_in[20]};
    const float* prelu  = (const float*)d_in[21];
    const float* pscale = (const float*)d_in[22];
    float* out = (float*)d_out;

    float *t1, *f1, *t2, *f2, *t3, *f3, *zb, *zr, *acc;
    cudaGetSymbolAddress((void**)&t1, g_t1);
    cudaGetSymbolAddress((void**)&f1, g_f1);
    cudaGetSymbolAddress((void**)&t2, g_t2);
    cudaGetSymbolAddress((void**)&f2, g_f2);
    cudaGetSymbolAddress((void**)&t3, g_t3);
    cudaGetSymbolAddress((void**)&f3, g_f3);
    cudaGetSymbolAddress((void**)&zb, g_z);
    cudaGetSymbolAddress((void**)&zr, g_zr);
    cudaGetSymbolAddress((void**)&acc, g_acc);

    // second-image slabs
    float* t1B = t1 + (size_t)BATCH * 32 * HW0;
    float* f1B = f1 + (size_t)BATCH * 32 * HW0;
    float* t2B = t2 + (size_t)BATCH * 64 * HW1;
    float* f2B = f2 + (size_t)BATCH * 64 * HW1;
    float* t3B = t3 + (size_t)BATCH * 96 * HW2;
    float* f3B = f3 + (size_t)BATCH * 96 * HW2;

    // ---- feature pyramids, both images per launch ----
    launch_conv(in0, in1, W_[0], Bi[0], prelu, 0, t1, t1B,  3, 32, 512, 512, 1);
    launch_conv(t1, t1B,  W_[1], Bi[1], prelu, 1, f1, f1B, 32, 32, 512, 512, 1);
    launch_conv(f1, f1B,  W_[2], Bi[2], prelu, 2, t2, t2B, 32, 64, 512, 512, 2);
    launch_conv(t2, t2B,  W_[3], Bi[3], prelu, 3, f2, f2B, 64, 64, 256, 256, 1);
    launch_conv(f2, f2B,  W_[4], Bi[4], prelu, 4, t3, t3B, 64, 96, 256, 256, 2);
    launch_conv(t3, t3B,  W_[5], Bi[5], prelu, 5, f3, f3B, 96, 96, 128, 128, 1);

    // ---- z maps (both directions) ----
    {
        dim3 g((HW0 + 255) / 256, 2 * BATCH);
        compute_z_k<<<g, 256>>>(in0, in1, flow01[0], flow10[0], pscale, zb, H0, W0);
    }

    // ---- splat + fused norm/backwarp, 3 scales (both directions batched) ----
    const size_t levelBase[3] = {0, (size_t)BATCH * 70 * HW0,
                                 (size_t)BATCH * 70 * HW0 + (size_t)BATCH * 128 * HW1};
    const float* featsA[3] = {f1, f2, f3};
    const float* featsB[3] = {f1B, f2B, f3B};
    const int featC[3] = {32, 64, 96};
    const int chTot[3] = {70, 128, 192};

    for (int s = 0; s < 3; s++) {
        const int h = 512 >> s, w = 512 >> s;
        const int hw = h * w;
        const float* zmap = zb;
        if (s > 0) {
            dim3 g((hw + 255) / 256, 2 * BATCH);
            resize1_k<<<g, 256>>>(zb, zr, 512, 512, h, w);
            zmap = zr;
        }
        cudaMemsetAsync(acc, 0, (size_t)2 * BATCH * 3 * hw * sizeof(float));
        dim3 g((hw + 255) / 256, 2 * BATCH);
        splat_k<<<g, 256>>>(flow01[s], flow10[s], zmap, tt, acc, h, w);
        if (s == 0) {
            backwarp_norm_k<<<g, 256>>>(acc, featsA[0], featsB[0], in0, in1,
                                        out, featC[0], h, w, chTot[0],
                                        3, 38, 0, 35);
        } else {
            backwarp_norm_k<<<g, 256>>>(acc, featsA[s], featsB[s],
                                        (const float*)nullptr, (const float*)nullptr,
                                        out + levelBase[s], featC[s], h, w, chTot[s],
                                        0, featC[s], 0, 0);
        }
    }
    (void)in_sizes; (void)n_in; (void)out_size;
}

// round 10
// speedup vs baseline: 1.6707x; 1.6707x over previous
#include <cuda_runtime.h>
#include <math.h>

#define BATCH 2
#define H0 512
#define W0 512
#define HW0 (H0*W0)
#define HW1 (256*256)
#define HW2 (128*128)

typedef unsigned long long u64;

// ---------------- scratch (device globals; no allocations allowed) ----------------
// dual-image layout: [img0 batch slab][img1 batch slab]
__device__ float g_t1[2*BATCH*32*HW0];
__device__ float g_f1[2*BATCH*32*HW0];
__device__ float g_t2[2*BATCH*64*HW1];
__device__ float g_f2[2*BATCH*64*HW1];
__device__ float g_t3[2*BATCH*96*HW2];
__device__ float g_f3[2*BATCH*96*HW2];
__device__ float g_z [2*BATCH*HW0];      // z maps, both directions
__device__ float g_zr[2*BATCH*HW1];      // resized z
__device__ float g_acc[2*BATCH*3*HW0];   // splat accumulators, both directions

// ---------------- packed f32x2 helpers ----------------
__device__ __forceinline__ u64 dup2(float v) {
    u64 r; asm("mov.b64 %0, {%1, %1};" : "=l"(r) : "f"(v)); return r;
}
__device__ __forceinline__ u64 pack2(float lo, float hi) {
    u64 r; asm("mov.b64 %0, {%1, %2};" : "=l"(r) : "f"(lo), "f"(hi)); return r;
}
__device__ __forceinline__ void ffma2(u64 &acc, u64 w, u64 v) {
    asm("fma.rn.f32x2 %0, %1, %2, %0;" : "+l"(acc) : "l"(w), "l"(v));
}
__device__ __forceinline__ float2 unp2(u64 a) {
    float2 r; asm("mov.b64 {%0, %1}, %2;" : "=f"(r.x), "=f"(r.y) : "l"(a)); return r;
}

// ---------------- conv3x3 + PReLU, v4 ----------------
// 128 threads/block, 4 consecutive output pixels x 8 output channels per thread
// (channel pairs packed into f32x2 accumulators, FFMA2 path).
// Input loads per row per cin: one aligned LDG.128 for the thread's own 4 (stride-1)
// or two LDG.128 for 8 (stride-2) input pixels, plus 2 bounds-checked scalar halo
// LDGs (L1 hits; no shuffles, no cross-lane dependencies).
// Both images processed in one launch (blockIdx.z in [0, 2*BATCH)).
template<int STRIDE>
__global__ void __launch_bounds__(128)
conv3x3_v4(const float* __restrict__ inA, const float* __restrict__ inB,
           const float* __restrict__ wgt, const float* __restrict__ bias,
           const float* __restrict__ prelu_a, int aidx,
           float* __restrict__ outA, float* __restrict__ outB,
           int Cin, int Cout, int Hin, int Win, int Hout, int Wout)
{
    extern __shared__ u64 w_s[];   // [Cin][9 taps][4 channel-pairs]
    const int tid = threadIdx.x;
    const int zz = blockIdx.z;                 // 0..2*BATCH-1
    const int b  = zz & (BATCH - 1);
    const float* in  = (zz < BATCH) ? inA  : inB;
    float*       out = (zz < BATCH) ? outA : outB;
    const int co_base = blockIdx.y * 8;
    const int nW = Cin * 9;

    for (int i = tid; i < Cin * 36; i += 128) {
        int q = i & 3, rest = i >> 2;
        int tap = rest % 9, ci = rest / 9;
        w_s[i] = pack2(wgt[(size_t)(co_base + 2*q    ) * nW + ci*9 + tap],
                       wgt[(size_t)(co_base + 2*q + 1) * nW + ci*9 + tap]);
    }
    __syncthreads();

    const int base = (blockIdx.x * 128 + tid) * 4;   // 4 consecutive output pixels
    const int oy = base / Wout;
    const int ox = base - oy * Wout;
    const int bx = ox * STRIDE;                      // input x of first pixel
    const bool hasL = (ox > 0);
    const bool hasR = (bx + 4 * STRIDE < Win);

    u64 acc[4][4];
    #pragma unroll
    for (int p = 0; p < 4; p++)
        #pragma unroll
        for (int q = 0; q < 4; q++) acc[p][q] = 0ULL;

    const int HWin = Hin * Win;
    const float* chan = in + (size_t)b * Cin * HWin;

    for (int ci = 0; ci < Cin; ci++, chan += HWin) {
        const u64* wrow = w_s + ci * 36;
        #pragma unroll
        for (int r = 0; r < 3; r++) {
            const int iy = oy * STRIDE + r - 1;
            if ((unsigned)iy >= (unsigned)Hin) continue;   // warp-uniform
            const float* row = chan + (size_t)iy * Win;
            if (STRIDE == 1) {
                float4 Cv = __ldg((const float4*)(row + bx));
                float vm1 = hasL ? __ldg(row + bx - 1) : 0.f;
                float v4  = hasR ? __ldg(row + bx + 4) : 0.f;
                u64 vd[6];
                vd[0] = dup2(vm1);  vd[1] = dup2(Cv.x); vd[2] = dup2(Cv.y);
                vd[3] = dup2(Cv.z); vd[4] = dup2(Cv.w); vd[5] = dup2(v4);
                #pragma unroll
                for (int dx = 0; dx < 3; dx++) {
                    const u64* wt = wrow + (r * 3 + dx) * 4;
                    u64 w0 = wt[0], w1 = wt[1], w2 = wt[2], w3 = wt[3];
                    #pragma unroll
                    for (int p = 0; p < 4; p++) {
                        u64 vv = vd[p + dx];
                        ffma2(acc[p][0], w0, vv); ffma2(acc[p][1], w1, vv);
                        ffma2(acc[p][2], w2, vv); ffma2(acc[p][3], w3, vv);
                    }
                }
            } else {
                float4 C0 = __ldg((const float4*)(row + bx));
                float4 C1 = __ldg((const float4*)(row + bx + 4));
                float vm1 = hasL ? __ldg(row + bx - 1) : 0.f;
                float v8  = hasR ? __ldg(row + bx + 8) : 0.f;
                u64 vd[10];
                vd[0] = dup2(vm1);
                vd[1] = dup2(C0.x); vd[2] = dup2(C0.y); vd[3] = dup2(C0.z); vd[4] = dup2(C0.w);
                vd[5] = dup2(C1.x); vd[6] = dup2(C1.y); vd[7] = dup2(C1.z); vd[8] = dup2(C1.w);
                vd[9] = dup2(v8);
                #pragma unroll
                for (int dx = 0; dx < 3; dx++) {
                    const u64* wt = wrow + (r * 3 + dx) * 4;
                    u64 w0 = wt[0], w1 = wt[1], w2 = wt[2], w3 = wt[3];
                    #pragma unroll
                    for (int p = 0; p < 4; p++) {
                        u64 vv = vd[2 * p + dx];
                        ffma2(acc[p][0], w0, vv); ffma2(acc[p][1], w1, vv);
                        ffma2(acc[p][2], w2, vv); ffma2(acc[p][3], w3, vv);
                    }
                }
            }
        }
    }

    const float alpha = prelu_a[aidx];
    const int HWout = Hout * Wout;
    float* ob = out + ((size_t)b * Cout + co_base) * HWout + base;
    #pragma unroll
    for (int q = 0; q < 4; q++) {
        float blo = bias[co_base + 2*q], bhi = bias[co_base + 2*q + 1];
        float4 olo, ohi;
        float* plo = &olo.x; float* phi = &ohi.x;
        #pragma unroll
        for (int p = 0; p < 4; p++) {
            float2 a = unp2(acc[p][q]);
            float rl = a.x + blo; rl = (rl >= 0.f) ? rl : alpha * rl;
            float rh = a.y + bhi; rh = (rh >= 0.f) ? rh : alpha * rh;
            plo[p] = rl; phi[p] = rh;
        }
        *(float4*)(ob + (size_t)(2*q    ) * HWout) = olo;
        *(float4*)(ob + (size_t)(2*q + 1) * HWout) = ohi;
    }
}

// ---------------- z maps, both directions in one launch ----------------
__global__ void compute_z_k(const float* __restrict__ in0,
                            const float* __restrict__ in1,
                            const float* __restrict__ flow01,
                            const float* __restrict__ flow10,
                            const float* __restrict__ pscale,
                            float* __restrict__ z, int H, int W)
{
    const int zz = blockIdx.y;              // 0..2*BATCH-1
    const int d = zz / BATCH, b = zz % BATCH;
    const int p = blockIdx.x * blockDim.x + threadIdx.x;
    const int HW = H * W;
    if (p >= HW) return;
    const int y = p / W;
    const int x = p - y * W;

    const float* i0 = d ? in1 : in0;
    const float* i1 = d ? in0 : in1;
    const float* flow = d ? flow10 : flow01;

    const float fx = flow[((size_t)b * 2 + 0) * HW + p];
    const float fy = flow[((size_t)b * 2 + 1) * HW + p];
    float px = fminf(fmaxf((float)x + fx, 0.f), (float)(W - 1));
    float py = fminf(fmaxf((float)y + fy, 0.f), (float)(H - 1));
    float x0f = floorf(px), y0f = floorf(py);
    int x0 = (int)x0f, y0 = (int)y0f;
    int x1 = min(x0 + 1, W - 1), y1 = min(y0 + 1, H - 1);
    float wx = px - x0f, wy = py - y0f;
    float w00 = (1.f - wx) * (1.f - wy);
    float w10 = wx * (1.f - wy);
    float w01 = (1.f - wx) * wy;
    float w11 = wx * wy;

    float err = 0.f;
    #pragma unroll
    for (int c = 0; c < 3; c++) {
        const float* s = i1 + ((size_t)b * 3 + c) * HW;
        float g = s[y0 * W + x0] * w00 + s[y0 * W + x1] * w10 +
                  s[y1 * W + x0] * w01 + s[y1 * W + x1] * w11;
        float a = i0[((size_t)b * 3 + c) * HW + p];
        err += fabsf((2.f * a - 1.f) - (2.f * g - 1.f));
    }
    z[(size_t)zz * HW + p] = pscale[0] * (err * (1.f / 3.f));
}

// ---------------- bilinear resize of z, all 4 (d,b) slabs ----------------
__global__ void resize1_k(const float* __restrict__ in, float* __restrict__ out,
                          int Hin, int Win, int Hout, int Wout)
{
    const int zz = blockIdx.y;
    const int p = blockIdx.x * blockDim.x + threadIdx.x;
    const int HWo = Hout * Wout;
    if (p >= HWo) return;
    const int y = p / Wout;
    const int x = p - y * Wout;

    const float ry = (float)Hin / (float)Hout;
    const float rx = (float)Win / (float)Wout;
    float py = fminf(fmaxf(((float)y + 0.5f) * ry - 0.5f, 0.f), (float)(Hin - 1));
    float px = fminf(fmaxf(((float)x + 0.5f) * rx - 0.5f, 0.f), (float)(Win - 1));
    float y0f = floorf(py), x0f = floorf(px);
    int y0 = (int)y0f, x0 = (int)x0f;
    int y1 = min(y0 + 1, Hin - 1), x1 = min(x0 + 1, Win - 1);
    float wy = py - y0f, wx = px - x0f;

    const float* s = in + (size_t)zz * Hin * Win;
    float top = s[y0 * Win + x0] * (1.f - wx) + s[y0 * Win + x1] * wx;
    float bot = s[y1 * Win + x0] * (1.f - wx) + s[y1 * Win + x1] * wx;
    out[(size_t)zz * HWo + p] = top * (1.f - wy) + bot * wy;
}

// ---------------- softsplat scatter, both directions in one launch ----------------
__global__ void splat_k(const float* __restrict__ flowA,
                        const float* __restrict__ flowB,
                        const float* __restrict__ zmap,
                        const float* __restrict__ tt,
                        float* __restrict__ acc, int H, int W)
{
    const int zz = blockIdx.y;
    const int d = zz / BATCH, b = zz % BATCH;
    const int p = blockIdx.x * blockDim.x + threadIdx.x;
    const int HW = H * W;
    if (p >= HW) return;
    const int y = p / W;
    const int x = p - y * W;

    const float* flow = d ? flowB : flowA;
    float t = tt[b];
    if (d) t = 1.f - t;
    const float fx = t * flow[((size_t)b * 2 + 0) * HW + p];
    const float fy = t * flow[((size_t)b * 2 + 1) * HW + p];
    const float ez = expf(zmap[(size_t)zz * HW + p]);
    const float v0 = -fx * ez;
    const float v1 = -fy * ez;

    const float X = (float)x + fx;
    const float Y = (float)y + fy;
    const float x0f = floorf(X), y0f = floorf(Y);
    const int x0 = (int)x0f, y0 = (int)y0f;
    const float wx1 = X - x0f, wy1 = Y - y0f;
    const float wx0 = 1.f - wx1, wy0 = 1.f - wy1;

    float* a0 = acc + ((size_t)zz * 3 + 0) * HW;
    float* a1 = acc + ((size_t)zz * 3 + 1) * HW;
    float* a2 = acc + ((size_t)zz * 3 + 2) * HW;

    int cxs[4] = {x0, x0 + 1, x0,     x0 + 1};
    int cys[4] = {y0, y0,     y0 + 1, y0 + 1};
    float cws[4] = {wx0 * wy0, wx1 * wy0, wx0 * wy1, wx1 * wy1};
    #pragma unroll
    for (int k = 0; k < 4; k++) {
        int cx = cxs[k], cy = cys[k];
        if (cx >= 0 && cx < W && cy >= 0 && cy < H) {
            int idx = cy * W + cx;
            float cw = cws[k];
            atomicAdd(a0 + idx, v0 * cw);
            atomicAdd(a1 + idx, v1 * cw);
            atomicAdd(a2 + idx, ez * cw);
        }
    }
}

// ---------------- fused normalize + backwarp (feat, and img at s=0) ----------------
__global__ void backwarp_norm_k(const float* __restrict__ acc,
                                const float* __restrict__ featA,
                                const float* __restrict__ featB,
                                const float* __restrict__ imgA,   // null if s>0
                                const float* __restrict__ imgB,
                                float* __restrict__ out,          // level base
                                int C, int H, int W, int chTot,
                                int fOffA, int fOffB, int iOffA, int iOffB)
{
    const int zz = blockIdx.y;
    const int d = zz / BATCH, b = zz % BATCH;
    const int p = blockIdx.x * blockDim.x + threadIdx.x;
    const int HW = H * W;
    if (p >= HW) return;
    const int y = p / W;
    const int x = p - y * W;

    const float* a = acc + (size_t)zz * 3 * HW;
    float inv = 1.f / (a[2 * (size_t)HW + p] + 1e-7f);
    const float fx = a[p] * inv;
    const float fy = a[(size_t)HW + p] * inv;

    float px = fminf(fmaxf((float)x + fx, 0.f), (float)(W - 1));
    float py = fminf(fmaxf((float)y + fy, 0.f), (float)(H - 1));
    float x0f = floorf(px), y0f = floorf(py);
    int x0 = (int)x0f, y0 = (int)y0f;
    int x1 = min(x0 + 1, W - 1), y1 = min(y0 + 1, H - 1);
    float wx = px - x0f, wy = py - y0f;
    float w00 = (1.f - wx) * (1.f - wy);
    float w10 = wx * (1.f - wy);
    float w01 = (1.f - wx) * wy;
    float w11 = wx * wy;
    int i00 = y0 * W + x0, i10 = y0 * W + x1;
    int i01 = y1 * W + x0, i11 = y1 * W + x1;

    const float* feat = (d ? featB : featA) + (size_t)b * C * HW;
    const int fOff = d ? fOffB : fOffA;
    for (int c = 0; c < C; c++) {
        const float* s = feat + (size_t)c * HW;
        float g = s[i00] * w00 + s[i10] * w10 + s[i01] * w01 + s[i11] * w11;
        out[((size_t)b * chTot + fOff + c) * HW + p] = g;
    }
    if (imgA) {
        const float* img = (d ? imgB : imgA) + (size_t)b * 3 * HW;
        const int iOff = d ? iOffB : iOffA;
        #pragma unroll
        for (int c = 0; c < 3; c++) {
            const float* s = img + (size_t)c * HW;
            float g = s[i00] * w00 + s[i10] * w10 + s[i01] * w01 + s[i11] * w11;
            out[((size_t)b * chTot + iOff + c) * HW + p] = g;
        }
    }
}

// ---------------- host orchestration ----------------
static void launch_conv(const float* inA, const float* inB,
                        const float* w, const float* bias,
                        const float* prelu_a, int aidx,
                        float* outA, float* outB,
                        int Cin, int Cout, int Hin, int Win, int stride)
{
    int Hout = Hin / stride, Wout = Win / stride;
    dim3 grid((Hout * Wout) / 512, Cout / 8, 2 * BATCH);
    size_t smem = (size_t)Cin * 36 * sizeof(u64);
    if (stride == 1)
        conv3x3_v4<1><<<grid, 128, smem>>>(inA, inB, w, bias, prelu_a, aidx,
                                           outA, outB, Cin, Cout, Hin, Win, Hout, Wout);
    else
        conv3x3_v4<2><<<grid, 128, smem>>>(inA, inB, w, bias, prelu_a, aidx,
                                           outA, outB, Cin, Cout, Hin, Win, Hout, Wout);
}

extern "C" void kernel_launch(void* const* d_in, const int* in_sizes, int n_in,
                              void* d_out, int out_size)
{
    const float* in0   = (const float*)d_in[0];
    const float* in1   = (const float*)d_in[1];
    const float* tt    = (const float*)d_in[2];
    const float* flow01[3] = {(const float*)d_in[3], (const float*)d_in[4], (const float*)d_in[5]};
    const float* flow10[3] = {(const float*)d_in[6], (const float*)d_in[7], (const float*)d_in[8]};
    const float* W_[6]  = {(const float*)d_in[9],  (const float*)d_in[11], (const float*)d_in[13],
                           (const float*)d_in[15], (const float*)d_in[17], (const float*)d_in[19]};
    const float* Bi[6]  = {(const float*)d_in[10], (const float*)d_in[12], (const float*)d_in[14],
                           (const float*)d_in[16], (const float*)d_in[18], (const float*)d_in[20]};
    const float* prelu  = (const float*)d_in[21];
    const float* pscale = (const float*)d_in[22];
    float* out = (float*)d_out;

    float *t1, *f1, *t2, *f2, *t3, *f3, *zb, *zr, *acc;
    cudaGetSymbolAddress((void**)&t1, g_t1);
    cudaGetSymbolAddress((void**)&f1, g_f1);
    cudaGetSymbolAddress((void**)&t2, g_t2);
    cudaGetSymbolAddress((void**)&f2, g_f2);
    cudaGetSymbolAddress((void**)&t3, g_t3);
    cudaGetSymbolAddress((void**)&f3, g_f3);
    cudaGetSymbolAddress((void**)&zb, g_z);
    cudaGetSymbolAddress((void**)&zr, g_zr);
    cudaGetSymbolAddress((void**)&acc, g_acc);

    // second-image slabs
    float* t1B = t1 + (size_t)BATCH * 32 * HW0;
    float* f1B = f1 + (size_t)BATCH * 32 * HW0;
    float* t2B = t2 + (size_t)BATCH * 64 * HW1;
    float* f2B = f2 + (size_t)BATCH * 64 * HW1;
    float* t3B = t3 + (size_t)BATCH * 96 * HW2;
    float* f3B = f3 + (size_t)BATCH * 96 * HW2;

    // ---- feature pyramids, both images per launch ----
    launch_conv(in0, in1, W_[0], Bi[0], prelu, 0, t1, t1B,  3, 32, 512, 512, 1);
    launch_conv(t1, t1B,  W_[1], Bi[1], prelu, 1, f1, f1B, 32, 32, 512, 512, 1);
    launch_conv(f1, f1B,  W_[2], Bi[2], prelu, 2, t2, t2B, 32, 64, 512, 512, 2);
    launch_conv(t2, t2B,  W_[3], Bi[3], prelu, 3, f2, f2B, 64, 64, 256, 256, 1);
    launch_conv(f2, f2B,  W_[4], Bi[4], prelu, 4, t3, t3B, 64, 96, 256, 256, 2);
    launch_conv(t3, t3B,  W_[5], Bi[5], prelu, 5, f3, f3B, 96, 96, 128, 128, 1);

    // ---- z maps (both directions) ----
    {
        dim3 g((HW0 + 255) / 256, 2 * BATCH);
        compute_z_k<<<g, 256>>>(in0, in1, flow01[0], flow10[0], pscale, zb, H0, W0);
    }

    // ---- splat + fused norm/backwarp, 3 scales (both directions batched) ----
    const size_t levelBase[3] = {0, (size_t)BATCH * 70 * HW0,
                                 (size_t)BATCH * 70 * HW0 + (size_t)BATCH * 128 * HW1};
    const float* featsA[3] = {f1, f2, f3};
    const float* featsB[3] = {f1B, f2B, f3B};
    const int featC[3] = {32, 64, 96};
    const int chTot[3] = {70, 128, 192};

    for (int s = 0; s < 3; s++) {
        const int h = 512 >> s, w = 512 >> s;
        const int hw = h * w;
        const float* zmap = zb;
        if (s > 0) {
            dim3 g((hw + 255) / 256, 2 * BATCH);
            resize1_k<<<g, 256>>>(zb, zr, 512, 512, h, w);
            zmap = zr;
        }
        cudaMemsetAsync(acc, 0, (size_t)2 * BATCH * 3 * hw * sizeof(float));
        dim3 g((hw + 255) / 256, 2 * BATCH);
        splat_k<<<g, 256>>>(flow01[s], flow10[s], zmap, tt, acc, h, w);
        if (s == 0) {
            backwarp_norm_k<<<g, 256>>>(acc, featsA[0], featsB[0], in0, in1,
                                        out, featC[0], h, w, chTot[0],
                                        3, 38, 0, 35);
        } else {
            backwarp_norm_k<<<g, 256>>>(acc, featsA[s], featsB[s],
                                        (const float*)nullptr, (const float*)nullptr,
                                        out + levelBase[s], featC[s], h, w, chTot[s],
                                        0, featC[s], 0, 0);
        }
    }
    (void)in_sizes; (void)n_in; (void)out_size;
}